// round 2
// baseline (speedup 1.0000x reference)
#include <cuda_runtime.h>
#include <math.h>

#define N_NODES 50000
#define F_IN    1433
#define HDIM    256
#define NCLS    7

// ---------------- scratch (static device allocations; no cudaMalloc) ----------------
__device__ float g_deg[N_NODES];
__device__ float g_dinv[N_NODES];
__device__ float g_h[N_NODES * HDIM];     // GEMM output (pre-aggregation)
__device__ float g_a[N_NODES * HDIM];     // aggregation output (next layer input)
__device__ float g_h3[N_NODES * 8];       // layer-3 GEMM output (padded stride 8)
__device__ float g_a3[N_NODES * 8];       // layer-3 aggregation output

// ---------------- degree / normalization ----------------
__global__ void k_deg_init() {
    int i = blockIdx.x * blockDim.x + threadIdx.x;
    if (i < N_NODES) g_deg[i] = 1.0f;  // self-loop contribution
}

__global__ void k_deg_edges(const int* __restrict__ dst, int E) {
    int e = blockIdx.x * blockDim.x + threadIdx.x;
    if (e < E) atomicAdd(&g_deg[dst[e]], 1.0f);
}

__global__ void k_dinv() {
    int i = blockIdx.x * blockDim.x + threadIdx.x;
    if (i < N_NODES) g_dinv[i] = rsqrtf(g_deg[i]);  // deg >= 1 always
}

// ---------------- tensor-core GEMM (3xTF32 split precision) ----------------
// C[M,Nf] = op(A)[M,K] @ B[K,Nf], A,B,C row-major fp32.
// BM=128, BN=64, BK=32. 256 threads = 8 warps in 4(m) x 2(n); warp tile 32x32.
// Precision: a = a_hi + a_lo (both tf32); C += Ahi*Bhi + Ahi*Blo + Alo*Bhi.

__device__ __forceinline__ unsigned f2tf32(float f) {
    unsigned r;
    asm("cvt.rna.tf32.f32 %0, %1;" : "=r"(r) : "f"(f));
    return r;
}

#define TC_BM 128
#define TC_BN 64
#define TC_BK 32
#define TC_SS 36            // smem row stride (floats): (4m+k)%32 distinct -> conflict-free
#define TC_ASZ (TC_BM * TC_SS)
#define TC_BSZ (TC_BN * TC_SS)

__device__ __forceinline__ void mma_tf32(float c[4], unsigned a0, unsigned a1,
                                         unsigned a2, unsigned a3,
                                         unsigned b0, unsigned b1) {
    asm volatile(
        "mma.sync.aligned.m16n8k8.row.col.f32.tf32.tf32.f32 "
        "{%0,%1,%2,%3}, {%4,%5,%6,%7}, {%8,%9}, {%0,%1,%2,%3};\n"
        : "+f"(c[0]), "+f"(c[1]), "+f"(c[2]), "+f"(c[3])
        : "r"(a0), "r"(a1), "r"(a2), "r"(a3), "r"(b0), "r"(b1));
}

template<bool RELU>
__global__ __launch_bounds__(256)
void k_gemm_tc(const float* __restrict__ A, const float* __restrict__ B,
               float* __restrict__ Cmat, int M, int K, int Nf) {
    extern __shared__ unsigned smem_u[];
    unsigned* As_hi = smem_u;
    unsigned* As_lo = As_hi + TC_ASZ;
    unsigned* Bs_hi = As_lo + TC_ASZ;
    unsigned* Bs_lo = Bs_hi + TC_BSZ;

    const int tid  = threadIdx.x;
    const int warp = tid >> 5;
    const int lane = tid & 31;
    const int m0 = blockIdx.x * TC_BM;
    const int n0 = blockIdx.y * TC_BN;
    const int wm = (warp >> 1) * 32;   // warp row offset within block tile
    const int wn = (warp & 1) * 32;    // warp col offset
    const int g  = lane >> 2;          // group id 0..7
    const int tg = lane & 3;           // thread-in-group 0..3

    float acc[2][4][4];
#pragma unroll
    for (int i = 0; i < 2; i++)
#pragma unroll
        for (int j = 0; j < 4; j++)
#pragma unroll
            for (int r = 0; r < 4; r++) acc[i][j][r] = 0.0f;

    for (int k0 = 0; k0 < K; k0 += TC_BK) {
        // ---- load A tile 128x32 (16 elems/thread, coalesced along k) ----
#pragma unroll
        for (int it = 0; it < 16; it++) {
            int idx = it * 256 + tid;
            int k = idx & 31, m = idx >> 5;
            int gm = m0 + m, gk = k0 + k;
            float v = 0.0f;
            if (gm < M && gk < K) v = A[(long)gm * K + gk];
            if (RELU) v = fmaxf(v, 0.0f);
            unsigned hi = f2tf32(v);
            float lof = v - __uint_as_float(hi);
            As_hi[m * TC_SS + k] = hi;
            As_lo[m * TC_SS + k] = f2tf32(lof);
        }
        // ---- load B tile 32x64, transposed into Bs[n][k] ----
#pragma unroll
        for (int it = 0; it < 8; it++) {
            int idx = it * 256 + tid;
            int n = idx & 63, k = idx >> 6;
            int gk = k0 + k;
            float v = (gk < K) ? B[(long)gk * Nf + n0 + n] : 0.0f;
            unsigned hi = f2tf32(v);
            float lof = v - __uint_as_float(hi);
            Bs_hi[n * TC_SS + k] = hi;
            Bs_lo[n * TC_SS + k] = f2tf32(lof);
        }
        __syncthreads();

        // ---- compute: 4 k-steps of 8 ----
#pragma unroll
        for (int ks = 0; ks < TC_BK; ks += 8) {
            unsigned ah[2][4], al[2][4], bh[4][2], bl[4][2];
#pragma unroll
            for (int mi = 0; mi < 2; mi++) {
                int r0 = (wm + mi * 16 + g) * TC_SS + ks + tg;
                int r1 = r0 + 8 * TC_SS;
                ah[mi][0] = As_hi[r0];     ah[mi][1] = As_hi[r1];
                ah[mi][2] = As_hi[r0 + 4]; ah[mi][3] = As_hi[r1 + 4];
                al[mi][0] = As_lo[r0];     al[mi][1] = As_lo[r1];
                al[mi][2] = As_lo[r0 + 4]; al[mi][3] = As_lo[r1 + 4];
            }
#pragma unroll
            for (int nj = 0; nj < 4; nj++) {
                int c0 = (wn + nj * 8 + g) * TC_SS + ks + tg;
                bh[nj][0] = Bs_hi[c0]; bh[nj][1] = Bs_hi[c0 + 4];
                bl[nj][0] = Bs_lo[c0]; bl[nj][1] = Bs_lo[c0 + 4];
            }
#pragma unroll
            for (int mi = 0; mi < 2; mi++)
#pragma unroll
                for (int nj = 0; nj < 4; nj++) {
                    mma_tf32(acc[mi][nj], ah[mi][0], ah[mi][1], ah[mi][2], ah[mi][3],
                             bh[nj][0], bh[nj][1]);
                    mma_tf32(acc[mi][nj], ah[mi][0], ah[mi][1], ah[mi][2], ah[mi][3],
                             bl[nj][0], bl[nj][1]);
                    mma_tf32(acc[mi][nj], al[mi][0], al[mi][1], al[mi][2], al[mi][3],
                             bh[nj][0], bh[nj][1]);
                }
        }
        __syncthreads();
    }

    // ---- epilogue: each c-frag reg pair (c0,c1) and (c2,c3) are contiguous cols ----
#pragma unroll
    for (int mi = 0; mi < 2; mi++) {
        int row0 = m0 + wm + mi * 16 + g;
        int row1 = row0 + 8;
#pragma unroll
        for (int nj = 0; nj < 4; nj++) {
            int col = n0 + wn + nj * 8 + tg * 2;
            if (row0 < M)
                *reinterpret_cast<float2*>(&Cmat[(long)row0 * Nf + col]) =
                    make_float2(acc[mi][nj][0], acc[mi][nj][1]);
            if (row1 < M)
                *reinterpret_cast<float2*>(&Cmat[(long)row1 * Nf + col]) =
                    make_float2(acc[mi][nj][2], acc[mi][nj][3]);
        }
    }
}

// ---------------- aggregation (H=256): out = bias + self-loop, then edge scatter ----------------
__global__ void k_agg_init(const float* __restrict__ h, const float* __restrict__ bias,
                           float* __restrict__ out) {
    int idx = blockIdx.x * blockDim.x + threadIdx.x;
    int node = idx >> 6;
    int f4   = idx & 63;
    if (node >= N_NODES) return;
    float d = g_dinv[node];
    float s = d * d;
    float4 hv = reinterpret_cast<const float4*>(h)[node * 64 + f4];
    float4 bv = reinterpret_cast<const float4*>(bias)[f4];
    float4 o;
    o.x = bv.x + hv.x * s;
    o.y = bv.y + hv.y * s;
    o.z = bv.z + hv.z * s;
    o.w = bv.w + hv.w * s;
    reinterpret_cast<float4*>(out)[node * 64 + f4] = o;
}

__global__ void k_agg_edges(const float* __restrict__ h,
                            const int* __restrict__ src, const int* __restrict__ dst,
                            float* __restrict__ out, int E) {
    int t = blockIdx.x * blockDim.x + threadIdx.x;
    int e  = t >> 6;
    int f4 = t & 63;
    if (e >= E) return;
    int r = __ldg(&src[e]);
    int c = __ldg(&dst[e]);
    float nrm = g_dinv[r] * g_dinv[c];
    float4 hv = reinterpret_cast<const float4*>(h + (long)r * HDIM)[f4];
    float* o = out + (long)c * HDIM + f4 * 4;
    atomicAdd(o + 0, hv.x * nrm);
    atomicAdd(o + 1, hv.y * nrm);
    atomicAdd(o + 2, hv.z * nrm);
    atomicAdd(o + 3, hv.w * nrm);
}

// ---------------- layer 3: warp-per-row GEMM [N,256] x [256,7] with fused relu ----------------
__global__ __launch_bounds__(256)
void k_gemm3(const float* __restrict__ A, const float* __restrict__ W) {
    __shared__ float Ws[256 * NCLS];
    int tid = threadIdx.x;
    for (int i = tid; i < 256 * NCLS; i += 256) Ws[i] = W[i];
    __syncthreads();

    int warp = tid >> 5, lane = tid & 31;
    int row = blockIdx.x * 8 + warp;
    if (row >= N_NODES) return;

    float acc[NCLS];
#pragma unroll
    for (int c = 0; c < NCLS; c++) acc[c] = 0.0f;

    const float* a = A + (long)row * HDIM;
    for (int k = lane; k < HDIM; k += 32) {
        float v = fmaxf(a[k], 0.0f);
#pragma unroll
        for (int c = 0; c < NCLS; c++) acc[c] = fmaf(v, Ws[k * NCLS + c], acc[c]);
    }
#pragma unroll
    for (int c = 0; c < NCLS; c++) {
#pragma unroll
        for (int off = 16; off; off >>= 1)
            acc[c] += __shfl_down_sync(0xffffffffu, acc[c], off);
    }
    if (lane == 0) {
#pragma unroll
        for (int c = 0; c < NCLS; c++) g_h3[row * 8 + c] = acc[c];
    }
}

__global__ void k_agg3_init(const float* __restrict__ b3) {
    int t = blockIdx.x * blockDim.x + threadIdx.x;
    int node = t >> 3;
    int c    = t & 7;
    if (node >= N_NODES || c >= NCLS) return;
    float d = g_dinv[node];
    g_a3[node * 8 + c] = b3[c] + g_h3[node * 8 + c] * d * d;
}

__global__ void k_agg3_edges(const int* __restrict__ src, const int* __restrict__ dst, int E) {
    int t = blockIdx.x * blockDim.x + threadIdx.x;
    int e = t >> 3;
    int c = t & 7;
    if (e >= E || c >= NCLS) return;
    int r = __ldg(&src[e]);
    int d = __ldg(&dst[e]);
    float nrm = g_dinv[r] * g_dinv[d];
    atomicAdd(&g_a3[d * 8 + c], g_h3[r * 8 + c] * nrm);
}

__global__ void k_log_softmax(float* __restrict__ out) {
    int i = blockIdx.x * blockDim.x + threadIdx.x;
    if (i >= N_NODES) return;
    float v[NCLS];
    float m = -INFINITY;
#pragma unroll
    for (int c = 0; c < NCLS; c++) { v[c] = g_a3[i * 8 + c]; m = fmaxf(m, v[c]); }
    float s = 0.0f;
#pragma unroll
    for (int c = 0; c < NCLS; c++) s += __expf(v[c] - m);
    float lse = m + __logf(s);
#pragma unroll
    for (int c = 0; c < NCLS; c++) out[i * NCLS + c] = v[c] - lse;
}

// ---------------- launch ----------------
extern "C" void kernel_launch(void* const* d_in, const int* in_sizes, int n_in,
                              void* d_out, int out_size) {
    const float* x  = (const float*)d_in[0];
    const int*   ei = (const int*)d_in[1];
    const float* W1 = (const float*)d_in[2];
    const float* b1 = (const float*)d_in[3];
    const float* W2 = (const float*)d_in[4];
    const float* b2 = (const float*)d_in[5];
    const float* W3 = (const float*)d_in[6];
    const float* b3 = (const float*)d_in[7];
    float* out = (float*)d_out;

    const int E = in_sizes[1] / 2;
    const int* src = ei;       // edge_index[0]
    const int* dst = ei + E;   // edge_index[1]

    float *gh, *ga;
    cudaGetSymbolAddress((void**)&gh, g_h);
    cudaGetSymbolAddress((void**)&ga, g_a);

    const int smem_bytes = (2 * TC_ASZ + 2 * TC_BSZ) * 4;  // 55296 B
    static bool attr_done = false;
    if (!attr_done) {
        cudaFuncSetAttribute(k_gemm_tc<false>,
                             cudaFuncAttributeMaxDynamicSharedMemorySize, smem_bytes);
        cudaFuncSetAttribute(k_gemm_tc<true>,
                             cudaFuncAttributeMaxDynamicSharedMemorySize, smem_bytes);
        attr_done = true;
    }

    // 1) normalization coefficients
    k_deg_init<<<(N_NODES + 255) / 256, 256>>>();
    k_deg_edges<<<(E + 255) / 256, 256>>>(dst, E);
    k_dinv<<<(N_NODES + 255) / 256, 256>>>();

    dim3 gemm_grid((N_NODES + TC_BM - 1) / TC_BM, HDIM / TC_BN);

    // 2) layer 1: h = x @ W1 ; agg (+b1; relu fused into next gemm load)
    k_gemm_tc<false><<<gemm_grid, 256, smem_bytes>>>(x, W1, gh, N_NODES, F_IN, HDIM);
    {
        long t = (long)N_NODES * 64;
        k_agg_init<<<(unsigned)((t + 255) / 256), 256>>>(gh, b1, ga);
        long te = (long)E * 64;
        k_agg_edges<<<(unsigned)((te + 255) / 256), 256>>>(gh, src, dst, ga, E);
    }

    // 3) layer 2: h = relu(a) @ W2 ; agg
    k_gemm_tc<true><<<gemm_grid, 256, smem_bytes>>>(ga, W2, gh, N_NODES, HDIM, HDIM);
    {
        long t = (long)N_NODES * 64;
        k_agg_init<<<(unsigned)((t + 255) / 256), 256>>>(gh, b2, ga);
        long te = (long)E * 64;
        k_agg_edges<<<(unsigned)((te + 255) / 256), 256>>>(gh, src, dst, ga, E);
    }

    // 4) layer 3: h3 = relu(a) @ W3 ; agg ; log_softmax
    k_gemm3<<<(N_NODES + 7) / 8, 256>>>(ga, W3);
    {
        long t = (long)N_NODES * 8;
        k_agg3_init<<<(unsigned)((t + 255) / 256), 256>>>(b3);
        long te = (long)E * 8;
        k_agg3_edges<<<(unsigned)((te + 255) / 256), 256>>>(src, dst, E);
    }
    k_log_softmax<<<(N_NODES + 255) / 256, 256>>>(out);
}

// round 3
// speedup vs baseline: 3.0055x; 3.0055x over previous
#include <cuda_runtime.h>
#include <cuda_bf16.h>
#include <math.h>

#define N_NODES 50000
#define F_IN    1433
#define HDIM    256
#define NCLS    7

// ---------------- scratch (static device arrays; no cudaMalloc) ----------------
__device__ float g_deg[N_NODES];
__device__ float g_dinv[N_NODES];
__device__ float g_h[N_NODES * HDIM];     // GEMM output (pre-aggregation)
__device__ float g_a[N_NODES * HDIM];     // layer-1 aggregation output
__device__ float g_b[N_NODES * HDIM];     // layer-2 aggregation output
__device__ float g_h3[N_NODES * 8];       // layer-3 GEMM output (stride 8, pad=0)
__device__ float g_a3[N_NODES * 8];       // layer-3 aggregation output

// ---------------- vectorized global reduction ----------------
__device__ __forceinline__ void red_add_v4(float* p, float a, float b, float c, float d) {
    asm volatile("red.global.add.v4.f32 [%0], {%1,%2,%3,%4};"
                 :: "l"(p), "f"(a), "f"(b), "f"(c), "f"(d) : "memory");
}

// ---------------- degree / normalization ----------------
__global__ void k_deg_init() {
    int i = blockIdx.x * blockDim.x + threadIdx.x;
    if (i < N_NODES) g_deg[i] = 1.0f;
}
__global__ void k_deg_edges(const int* __restrict__ dst, int E) {
    int e = blockIdx.x * blockDim.x + threadIdx.x;
    if (e < E) atomicAdd(&g_deg[dst[e]], 1.0f);
}
__global__ void k_dinv() {
    int i = blockIdx.x * blockDim.x + threadIdx.x;
    if (i < N_NODES) g_dinv[i] = rsqrtf(g_deg[i]);
}

// =====================================================================
// bf16 split-precision tensor-core GEMM:  C[M,256] = op(A)[M,K] @ B[K,256]
// v = hi + lo (both bf16);  C += Ahi*Bhi + Ahi*Blo + Alo*Bhi  (fp32 acc)
// BM=128 BN=64 BK=32, 256 threads = 8 warps (4m x 2n), warp tile 32x32.
// A smem [128 rows][32 k] bf16, B smem [32 k][64 n] bf16 (ldmatrix.trans).
// 128B-pair swizzle for conflict-free ldmatrix.
// Epilogue writes C (=h) and Cagg = bias + dinv^2 * h  (fused agg-init).
// =====================================================================
#define BM 128
#define BN 64
#define BK 32

__device__ __forceinline__ int swzA(int m, int c) {      // A: 4 chunks(16B)/row
    return (m >> 1) * 8 + ((((m & 1) * 4) + c) ^ ((m >> 1) & 7));
}
__device__ __forceinline__ int swzB(int k, int c) {      // B: 8 chunks(16B)/row
    return k * 8 + (c ^ (k & 7));
}

__device__ __forceinline__ void ldsm_x4(unsigned r[4], const void* p) {
    unsigned a = (unsigned)__cvta_generic_to_shared(p);
    asm volatile("ldmatrix.sync.aligned.m8n8.x4.shared.b16 {%0,%1,%2,%3}, [%4];"
                 : "=r"(r[0]), "=r"(r[1]), "=r"(r[2]), "=r"(r[3]) : "r"(a));
}
__device__ __forceinline__ void ldsm_x4_t(unsigned r[4], const void* p) {
    unsigned a = (unsigned)__cvta_generic_to_shared(p);
    asm volatile("ldmatrix.sync.aligned.m8n8.x4.trans.shared.b16 {%0,%1,%2,%3}, [%4];"
                 : "=r"(r[0]), "=r"(r[1]), "=r"(r[2]), "=r"(r[3]) : "r"(a));
}
__device__ __forceinline__ void mma_bf16(float c[4], const unsigned a[4],
                                         unsigned b0, unsigned b1) {
    asm volatile(
        "mma.sync.aligned.m16n8k16.row.col.f32.bf16.bf16.f32 "
        "{%0,%1,%2,%3}, {%4,%5,%6,%7}, {%8,%9}, {%0,%1,%2,%3};"
        : "+f"(c[0]), "+f"(c[1]), "+f"(c[2]), "+f"(c[3])
        : "r"(a[0]), "r"(a[1]), "r"(a[2]), "r"(a[3]), "r"(b0), "r"(b1));
}

// split 8 fp32 into hi/lo bf16 packs and store one 16B chunk each
__device__ __forceinline__ void cvt_store8(uint4* hi_base, uint4* lo_base, int idx,
                                           const float* v) {
    unsigned h[4], l[4];
#pragma unroll
    for (int j = 0; j < 4; j++) {
        __nv_bfloat162 hb = __floats2bfloat162_rn(v[2*j], v[2*j+1]);
        float2 hf = __bfloat1622float2(hb);
        __nv_bfloat162 lb = __floats2bfloat162_rn(v[2*j] - hf.x, v[2*j+1] - hf.y);
        h[j] = *reinterpret_cast<unsigned*>(&hb);
        l[j] = *reinterpret_cast<unsigned*>(&lb);
    }
    hi_base[idx] = make_uint4(h[0], h[1], h[2], h[3]);
    lo_base[idx] = make_uint4(l[0], l[1], l[2], l[3]);
}

template<bool RELU>
__global__ __launch_bounds__(256, 2)
void k_gemm_bf3(const float* __restrict__ A, const float* __restrict__ B,
                float* __restrict__ C, float* __restrict__ Cagg,
                const float* __restrict__ bias, int M, int K) {
    __shared__ uint4 sAh[512], sAl[512], sBh[256], sBl[256];

    const int tid = threadIdx.x, warp = tid >> 5, lane = tid & 31;
    const int m0 = blockIdx.x * BM, n0 = blockIdx.y * BN;
    const int wm = (warp >> 1) * 32, wn = (warp & 1) * 32;
    const int g = lane >> 2, tg = lane & 3;

    // tile-load task assignment
    const int a_c = tid & 3, a_m = tid >> 2;        // A: (m, m+64) x chunk a_c
    const int b_k = tid >> 3, b_nc = tid & 7;       // B: row b_k, n-chunk b_nc

    float acc[2][4][4];
#pragma unroll
    for (int i = 0; i < 2; i++)
#pragma unroll
        for (int j = 0; j < 4; j++)
#pragma unroll
            for (int r = 0; r < 4; r++) acc[i][j][r] = 0.0f;

    float ra[2][8], rb[8];

    // ---- gmem load of one k-tile into registers ----
    auto loadA = [&](int k0) {
#pragma unroll
        for (int p = 0; p < 2; p++) {
            int gm = m0 + a_m + p * 64;
#pragma unroll
            for (int j = 0; j < 8; j++) {
                int gk = k0 + a_c * 8 + j;
                float v = (gm < M && gk < K) ? __ldg(&A[(long)gm * K + gk]) : 0.0f;
                if (RELU) v = fmaxf(v, 0.0f);
                ra[p][j] = v;
            }
        }
    };
    auto loadB = [&](int k0) {
        int gk = k0 + b_k;
        if (gk < K) {
            const float4* p4 = reinterpret_cast<const float4*>(&B[(long)gk * HDIM + n0 + b_nc * 8]);
            float4 v0 = __ldg(p4), v1 = __ldg(p4 + 1);
            rb[0]=v0.x; rb[1]=v0.y; rb[2]=v0.z; rb[3]=v0.w;
            rb[4]=v1.x; rb[5]=v1.y; rb[6]=v1.z; rb[7]=v1.w;
        } else {
#pragma unroll
            for (int j = 0; j < 8; j++) rb[j] = 0.0f;
        }
    };
    auto storeAB = [&]() {
        cvt_store8(sAh, sAl, swzA(a_m,      a_c), ra[0]);
        cvt_store8(sAh, sAl, swzA(a_m + 64, a_c), ra[1]);
        cvt_store8(sBh, sBl, swzB(b_k, b_nc), rb);
    };

    loadA(0); loadB(0);
    storeAB();
    __syncthreads();

    const int Kt = (K + BK - 1) / BK;
    for (int it = 0; it < Kt; it++) {
        const bool has_next = (it + 1 < Kt);
        if (has_next) { loadA((it + 1) * BK); loadB((it + 1) * BK); }

#pragma unroll
        for (int ks = 0; ks < 2; ks++) {                   // two k16 halves of BK
            unsigned ah[2][4], al[2][4], bh[2][4], bl[2][4];
#pragma unroll
            for (int mi = 0; mi < 2; mi++) {
                int row = wm + mi * 16 + (lane & 15);
                int c = ks * 2 + (lane >> 4);
                ldsm_x4(ah[mi], &sAh[swzA(row, c)]);
                ldsm_x4(al[mi], &sAl[swzA(row, c)]);
            }
#pragma unroll
            for (int njp = 0; njp < 2; njp++) {
                int krow = ks * 16 + ((lane >> 3) & 1) * 8 + (lane & 7);
                int c = (wn >> 3) + 2 * njp + (lane >> 4);
                ldsm_x4_t(bh[njp], &sBh[swzB(krow, c)]);
                ldsm_x4_t(bl[njp], &sBl[swzB(krow, c)]);
            }
#pragma unroll
            for (int mi = 0; mi < 2; mi++)
#pragma unroll
                for (int njp = 0; njp < 2; njp++)
#pragma unroll
                    for (int sub = 0; sub < 2; sub++) {
                        int nj = njp * 2 + sub;
                        mma_bf16(acc[mi][nj], ah[mi], bh[njp][2*sub], bh[njp][2*sub+1]);
                        mma_bf16(acc[mi][nj], ah[mi], bl[njp][2*sub], bl[njp][2*sub+1]);
                        mma_bf16(acc[mi][nj], al[mi], bh[njp][2*sub], bh[njp][2*sub+1]);
                    }
        }
        __syncthreads();
        if (has_next) { storeAB(); __syncthreads(); }
    }

    // ---- epilogue: write h and fused agg-init (bias + dinv^2 * h) ----
#pragma unroll
    for (int mi = 0; mi < 2; mi++) {
        int row0 = m0 + wm + mi * 16 + g;
        int row1 = row0 + 8;
        float s0 = 0.0f, s1 = 0.0f;
        if (row0 < M) { float d = g_dinv[row0]; s0 = d * d; }
        if (row1 < M) { float d = g_dinv[row1]; s1 = d * d; }
#pragma unroll
        for (int nj = 0; nj < 4; nj++) {
            int col = n0 + wn + nj * 8 + tg * 2;
            float2 bv = *reinterpret_cast<const float2*>(&bias[col]);
            if (row0 < M) {
                *reinterpret_cast<float2*>(&C[(long)row0 * HDIM + col]) =
                    make_float2(acc[mi][nj][0], acc[mi][nj][1]);
                *reinterpret_cast<float2*>(&Cagg[(long)row0 * HDIM + col]) =
                    make_float2(bv.x + s0 * acc[mi][nj][0], bv.y + s0 * acc[mi][nj][1]);
            }
            if (row1 < M) {
                *reinterpret_cast<float2*>(&C[(long)row1 * HDIM + col]) =
                    make_float2(acc[mi][nj][2], acc[mi][nj][3]);
                *reinterpret_cast<float2*>(&Cagg[(long)row1 * HDIM + col]) =
                    make_float2(bv.x + s1 * acc[mi][nj][2], bv.y + s1 * acc[mi][nj][3]);
            }
        }
    }
}

// ---------------- edge scatter (H=256): 64 threads/edge, one v4-red each ----------------
__global__ void k_agg_edges(const float* __restrict__ h,
                            const int* __restrict__ src, const int* __restrict__ dst,
                            float* __restrict__ out, int E) {
    int t = blockIdx.x * blockDim.x + threadIdx.x;
    int e = t >> 6;
    int f4 = t & 63;
    if (e >= E) return;
    int r = __ldg(&src[e]);
    int c = __ldg(&dst[e]);
    float nrm = g_dinv[r] * g_dinv[c];
    float4 hv = __ldg(reinterpret_cast<const float4*>(h + (long)r * HDIM) + f4);
    red_add_v4(out + (long)c * HDIM + f4 * 4,
               hv.x * nrm, hv.y * nrm, hv.z * nrm, hv.w * nrm);
}

// ---------------- layer 3: warp-per-row GEMM [N,256]x[256,7], fused agg-init ----------------
__global__ __launch_bounds__(256)
void k_gemm3(const float* __restrict__ A, const float* __restrict__ W,
             const float* __restrict__ b3) {
    __shared__ float Ws[256 * NCLS];
    int tid = threadIdx.x;
    for (int i = tid; i < 256 * NCLS; i += 256) Ws[i] = W[i];
    __syncthreads();

    int warp = tid >> 5, lane = tid & 31;
    int row = blockIdx.x * 8 + warp;
    if (row >= N_NODES) return;

    float acc[NCLS];
#pragma unroll
    for (int c = 0; c < NCLS; c++) acc[c] = 0.0f;

    const float* a = A + (long)row * HDIM;
    for (int k = lane; k < HDIM; k += 32) {
        float v = fmaxf(a[k], 0.0f);
#pragma unroll
        for (int c = 0; c < NCLS; c++) acc[c] = fmaf(v, Ws[k * NCLS + c], acc[c]);
    }
#pragma unroll
    for (int c = 0; c < NCLS; c++)
#pragma unroll
        for (int off = 16; off; off >>= 1)
            acc[c] += __shfl_down_sync(0xffffffffu, acc[c], off);

    if (lane == 0) {
        float d = g_dinv[row];
        float s = d * d;
#pragma unroll
        for (int c = 0; c < NCLS; c++) {
            g_h3[row * 8 + c] = acc[c];
            g_a3[row * 8 + c] = b3[c] + s * acc[c];
        }
        g_h3[row * 8 + 7] = 0.0f;
        g_a3[row * 8 + 7] = 0.0f;
    }
}

// one thread per edge: 2x v4-red of 7 (+pad) floats
__global__ void k_agg3_edges(const int* __restrict__ src, const int* __restrict__ dst, int E) {
    int e = blockIdx.x * blockDim.x + threadIdx.x;
    if (e >= E) return;
    int r = __ldg(&src[e]);
    int d = __ldg(&dst[e]);
    float nrm = g_dinv[r] * g_dinv[d];
    const float4* hp = reinterpret_cast<const float4*>(&g_h3[r * 8]);
    float4 v0 = __ldg(hp), v1 = __ldg(hp + 1);
    red_add_v4(&g_a3[d * 8],     v0.x * nrm, v0.y * nrm, v0.z * nrm, v0.w * nrm);
    red_add_v4(&g_a3[d * 8 + 4], v1.x * nrm, v1.y * nrm, v1.z * nrm, 0.0f);
}

__global__ void k_log_softmax(float* __restrict__ out) {
    int i = blockIdx.x * blockDim.x + threadIdx.x;
    if (i >= N_NODES) return;
    float v[NCLS];
    float m = -INFINITY;
#pragma unroll
    for (int c = 0; c < NCLS; c++) { v[c] = g_a3[i * 8 + c]; m = fmaxf(m, v[c]); }
    float s = 0.0f;
#pragma unroll
    for (int c = 0; c < NCLS; c++) s += __expf(v[c] - m);
    float lse = m + __logf(s);
#pragma unroll
    for (int c = 0; c < NCLS; c++) out[i * NCLS + c] = v[c] - lse;
}

// ---------------- launch ----------------
extern "C" void kernel_launch(void* const* d_in, const int* in_sizes, int n_in,
                              void* d_out, int out_size) {
    const float* x  = (const float*)d_in[0];
    const int*   ei = (const int*)d_in[1];
    const float* W1 = (const float*)d_in[2];
    const float* b1 = (const float*)d_in[3];
    const float* W2 = (const float*)d_in[4];
    const float* b2 = (const float*)d_in[5];
    const float* W3 = (const float*)d_in[6];
    const float* b3 = (const float*)d_in[7];
    float* out = (float*)d_out;

    const int E = in_sizes[1] / 2;
    const int* src = ei;       // edge_index[0]
    const int* dst = ei + E;   // edge_index[1]

    float *gh, *ga, *gb;
    cudaGetSymbolAddress((void**)&gh, g_h);
    cudaGetSymbolAddress((void**)&ga, g_a);
    cudaGetSymbolAddress((void**)&gb, g_b);

    // 1) normalization
    k_deg_init<<<(N_NODES + 255) / 256, 256>>>();
    k_deg_edges<<<(E + 255) / 256, 256>>>(dst, E);
    k_dinv<<<(N_NODES + 255) / 256, 256>>>();

    dim3 gemm_grid((N_NODES + BM - 1) / BM, HDIM / BN);
    long te = (long)E * 64;
    unsigned eblocks = (unsigned)((te + 255) / 256);

    // 2) layer 1: h = x@W1 ; epilogue writes h and a=b1+s*h ; edge scatter into a
    k_gemm_bf3<false><<<gemm_grid, 256>>>(x, W1, gh, ga, b1, N_NODES, F_IN);
    k_agg_edges<<<eblocks, 256>>>(gh, src, dst, ga, E);

    // 3) layer 2: h = relu(a)@W2 ; epilogue writes h and b=b2+s*h ; scatter into b
    k_gemm_bf3<true><<<gemm_grid, 256>>>(ga, W2, gh, gb, b2, N_NODES, HDIM);
    k_agg_edges<<<eblocks, 256>>>(gh, src, dst, gb, E);

    // 4) layer 3 + log_softmax
    k_gemm3<<<(N_NODES + 7) / 8, 256>>>(gb, W3, b3);
    k_agg3_edges<<<(E + 255) / 256, 256>>>(src, dst, E);
    k_log_softmax<<<(N_NODES + 255) / 256, 256>>>(out);
}

// round 4
// speedup vs baseline: 4.6361x; 1.5426x over previous
#include <cuda_runtime.h>
#include <cuda_bf16.h>
#include <math.h>

#define N_NODES 50000
#define F_IN    1433
#define KP1     1440          // F_IN padded to BK multiple
#define HDIM    256
#define NCLS    7
#define EDGES_MAX 800000

// ---------------- scratch (static device arrays; no cudaMalloc) ----------------
__device__ int   g_cnt[N_NODES];
__device__ int   g_off[N_NODES + 1];
__device__ int   g_cur[N_NODES];
__device__ float g_dinv[N_NODES];
__device__ int2  g_csr[EDGES_MAX];            // (src, norm-bits) grouped by dst

__device__ __align__(16) __nv_bfloat16 g_xh[(size_t)N_NODES * KP1];
__device__ __align__(16) __nv_bfloat16 g_xl[(size_t)N_NODES * KP1];
__device__ __align__(16) __nv_bfloat16 g_w1h[KP1 * HDIM];
__device__ __align__(16) __nv_bfloat16 g_w1l[KP1 * HDIM];
__device__ __align__(16) __nv_bfloat16 g_w2h[HDIM * HDIM];
__device__ __align__(16) __nv_bfloat16 g_w2l[HDIM * HDIM];
__device__ __align__(16) float g_h[(size_t)N_NODES * HDIM];          // GEMM out (fp32)
__device__ __align__(16) __nv_bfloat16 g_a1h[(size_t)N_NODES * HDIM]; // agg1 out, relu'd, split
__device__ __align__(16) __nv_bfloat16 g_a1l[(size_t)N_NODES * HDIM];
__device__ __align__(16) __nv_bfloat16 g_a2h[(size_t)N_NODES * HDIM];
__device__ __align__(16) __nv_bfloat16 g_a2l[(size_t)N_NODES * HDIM];
__device__ __align__(16) float g_h3[N_NODES * 8];
__device__ __align__(16) float g_a3[N_NODES * 8];

// ---------------- CSR build ----------------
__global__ void k_zero_cnt() {
    int i = blockIdx.x * blockDim.x + threadIdx.x;
    if (i < N_NODES) g_cnt[i] = 0;
}
__global__ void k_cnt_edges(const int* __restrict__ dst, int E) {
    int e = blockIdx.x * blockDim.x + threadIdx.x;
    if (e < E) atomicAdd(&g_cnt[dst[e]], 1);
}
__global__ void k_dinv() {
    int i = blockIdx.x * blockDim.x + threadIdx.x;
    if (i < N_NODES) g_dinv[i] = rsqrtf(1.0f + (float)g_cnt[i]);
}
// single-block exclusive scan over g_cnt -> g_off, g_cur
__global__ void k_scan() {
    __shared__ int wsum[32];
    __shared__ int carry;
    int tid = threadIdx.x, lane = tid & 31, w = tid >> 5;
    if (tid == 0) carry = 0;
    __syncthreads();
    int nCh = (N_NODES + 1023) / 1024;
    for (int ch = 0; ch < nCh; ch++) {
        int i = ch * 1024 + tid;
        int v = (i < N_NODES) ? g_cnt[i] : 0;
        int x = v;
#pragma unroll
        for (int o = 1; o < 32; o <<= 1) {
            int y = __shfl_up_sync(~0u, x, o);
            if (lane >= o) x += y;
        }
        if (lane == 31) wsum[w] = x;
        __syncthreads();
        if (w == 0) {
            int s = wsum[lane];
#pragma unroll
            for (int o = 1; o < 32; o <<= 1) {
                int y = __shfl_up_sync(~0u, s, o);
                if (lane >= o) s += y;
            }
            wsum[lane] = s;
        }
        __syncthreads();
        int incl = x + (w > 0 ? wsum[w - 1] : 0);
        int tot = wsum[31];
        if (i < N_NODES) {
            int ex = carry + incl - v;
            g_off[i] = ex;
            g_cur[i] = ex;
        }
        __syncthreads();
        if (tid == 0) carry += tot;
        __syncthreads();
    }
    if (tid == 0) g_off[N_NODES] = carry;
}
__global__ void k_csr_fill(const int* __restrict__ src, const int* __restrict__ dst, int E) {
    int e = blockIdx.x * blockDim.x + threadIdx.x;
    if (e >= E) return;
    int r = src[e], d = dst[e];
    int pos = atomicAdd(&g_cur[d], 1);
    g_csr[pos] = make_int2(r, __float_as_int(g_dinv[r] * g_dinv[d]));
}

// ---------------- operand prep: fp32 -> bf16 hi/lo (padded) ----------------
__device__ __forceinline__ void split4(const float v[4], unsigned h2[2], unsigned l2[2]) {
#pragma unroll
    for (int p = 0; p < 2; p++) {
        __nv_bfloat162 hb = __floats2bfloat162_rn(v[2 * p], v[2 * p + 1]);
        float2 hf = __bfloat1622float2(hb);
        __nv_bfloat162 lb = __floats2bfloat162_rn(v[2 * p] - hf.x, v[2 * p + 1] - hf.y);
        h2[p] = *reinterpret_cast<unsigned*>(&hb);
        l2[p] = *reinterpret_cast<unsigned*>(&lb);
    }
}
__global__ void k_split_x(const float* __restrict__ x) {
    long t = (long)blockIdx.x * blockDim.x + threadIdx.x;
    if (t >= (long)N_NODES * (KP1 / 4)) return;
    int row = (int)(t / (KP1 / 4));
    int c4  = (int)(t % (KP1 / 4));
    int k = c4 * 4;
    float v[4];
#pragma unroll
    for (int j = 0; j < 4; j++)
        v[j] = (k + j < F_IN) ? __ldg(&x[(long)row * F_IN + k + j]) : 0.0f;
    unsigned h2[2], l2[2];
    split4(v, h2, l2);
    *reinterpret_cast<uint2*>(&g_xh[(long)row * KP1 + k]) = make_uint2(h2[0], h2[1]);
    *reinterpret_cast<uint2*>(&g_xl[(long)row * KP1 + k]) = make_uint2(l2[0], l2[1]);
}
__global__ void k_split_w(const float* __restrict__ W, __nv_bfloat16* __restrict__ Wh,
                          __nv_bfloat16* __restrict__ Wl, int K, int Kp) {
    int t = blockIdx.x * blockDim.x + threadIdx.x;
    if (t >= Kp * (HDIM / 4)) return;
    int k = t / (HDIM / 4);
    int n4 = t % (HDIM / 4);
    float v[4] = {0.f, 0.f, 0.f, 0.f};
    if (k < K) {
        float4 f = __ldg(reinterpret_cast<const float4*>(&W[(long)k * HDIM + n4 * 4]));
        v[0] = f.x; v[1] = f.y; v[2] = f.z; v[3] = f.w;
    }
    unsigned h2[2], l2[2];
    split4(v, h2, l2);
    *reinterpret_cast<uint2*>(&Wh[(long)k * HDIM + n4 * 4]) = make_uint2(h2[0], h2[1]);
    *reinterpret_cast<uint2*>(&Wl[(long)k * HDIM + n4 * 4]) = make_uint2(l2[0], l2[1]);
}

// =====================================================================
// bf16 split-precision tensor-core GEMM with cp.async double buffering.
// C[M,256] = A[M,Kp] @ B[Kp,256]; A,B pre-split bf16 hi/lo.
// BM=128 BN=64 BK=32, 256 threads = 8 warps (4m x 2n), warp tile 32x32.
// =====================================================================
#define BM 128
#define BN 64
#define BK 32

__device__ __forceinline__ int swzA(int m, int c) {
    return (m >> 1) * 8 + ((((m & 1) * 4) + c) ^ ((m >> 1) & 7));
}
__device__ __forceinline__ int swzB(int k, int c) {
    return k * 8 + (c ^ (k & 7));
}
__device__ __forceinline__ void cp16(uint4* smem, const uint4* g, bool valid) {
    unsigned s = (unsigned)__cvta_generic_to_shared(smem);
    int sz = valid ? 16 : 0;
    asm volatile("cp.async.ca.shared.global [%0], [%1], 16, %2;"
                 :: "r"(s), "l"(g), "r"(sz));
}
__device__ __forceinline__ void cp_commit() { asm volatile("cp.async.commit_group;"); }
__device__ __forceinline__ void cp_wait_all() { asm volatile("cp.async.wait_group 0;"); }

__device__ __forceinline__ void ldsm_x4(unsigned r[4], const void* p) {
    unsigned a = (unsigned)__cvta_generic_to_shared(p);
    asm volatile("ldmatrix.sync.aligned.m8n8.x4.shared.b16 {%0,%1,%2,%3}, [%4];"
                 : "=r"(r[0]), "=r"(r[1]), "=r"(r[2]), "=r"(r[3]) : "r"(a));
}
__device__ __forceinline__ void ldsm_x4_t(unsigned r[4], const void* p) {
    unsigned a = (unsigned)__cvta_generic_to_shared(p);
    asm volatile("ldmatrix.sync.aligned.m8n8.x4.trans.shared.b16 {%0,%1,%2,%3}, [%4];"
                 : "=r"(r[0]), "=r"(r[1]), "=r"(r[2]), "=r"(r[3]) : "r"(a));
}
__device__ __forceinline__ void mma_bf16(float c[4], const unsigned a[4],
                                         unsigned b0, unsigned b1) {
    asm volatile(
        "mma.sync.aligned.m16n8k16.row.col.f32.bf16.bf16.f32 "
        "{%0,%1,%2,%3}, {%4,%5,%6,%7}, {%8,%9}, {%0,%1,%2,%3};"
        : "+f"(c[0]), "+f"(c[1]), "+f"(c[2]), "+f"(c[3])
        : "r"(a[0]), "r"(a[1]), "r"(a[2]), "r"(a[3]), "r"(b0), "r"(b1));
}

__global__ __launch_bounds__(256, 2)
void k_gemm_bf3(const __nv_bfloat16* __restrict__ Ah, const __nv_bfloat16* __restrict__ Al,
                const __nv_bfloat16* __restrict__ Bh, const __nv_bfloat16* __restrict__ Bl,
                float* __restrict__ C, int M, int Kp) {
    __shared__ uint4 sAh[2][512], sAl[2][512], sBh[2][256], sBl[2][256];

    const int tid = threadIdx.x, warp = tid >> 5, lane = tid & 31;
    const int m0 = blockIdx.x * BM, n0 = blockIdx.y * BN;
    const int wm = (warp >> 1) * 32, wn = (warp & 1) * 32;
    const int g = lane >> 2, tg = lane & 3;

    const uint4* Ah4 = reinterpret_cast<const uint4*>(Ah);
    const uint4* Al4 = reinterpret_cast<const uint4*>(Al);
    const uint4* Bh4 = reinterpret_cast<const uint4*>(Bh);
    const uint4* Bl4 = reinterpret_cast<const uint4*>(Bl);
    const int Kp4 = Kp >> 3;
    const int n08 = n0 >> 3;

    const int a_m = tid >> 2, a_c = tid & 3;
    const int b_k = tid >> 3, b_c = tid & 7;
    const int gm0 = m0 + a_m, gm1 = gm0 + 64;
    const bool v0 = gm0 < M, v1 = gm1 < M;
    const long aRow0 = (long)(v0 ? gm0 : 0) * Kp4;
    const long aRow1 = (long)(v1 ? gm1 : 0) * Kp4;
    const int sA0 = swzA(a_m, a_c), sA1 = swzA(a_m + 64, a_c);
    const int sB = swzB(b_k, b_c);

    auto issue = [&](int kt, int buf) {
        long ac = aRow0 + kt * 4 + a_c;
        long ac1 = aRow1 + kt * 4 + a_c;
        cp16(&sAh[buf][sA0], &Ah4[ac],  v0);
        cp16(&sAl[buf][sA0], &Al4[ac],  v0);
        cp16(&sAh[buf][sA1], &Ah4[ac1], v1);
        cp16(&sAl[buf][sA1], &Al4[ac1], v1);
        long bc = (long)(kt * 32 + b_k) * 32 + n08 + b_c;
        cp16(&sBh[buf][sB], &Bh4[bc], true);
        cp16(&sBl[buf][sB], &Bl4[bc], true);
        cp_commit();
    };

    float acc[2][4][4];
#pragma unroll
    for (int i = 0; i < 2; i++)
#pragma unroll
        for (int j = 0; j < 4; j++)
#pragma unroll
            for (int r = 0; r < 4; r++) acc[i][j][r] = 0.0f;

    const int Kt = Kp / BK;
    issue(0, 0);
    int cur = 0;
    for (int it = 0; it < Kt; it++) {
        cp_wait_all();
        __syncthreads();
        if (it + 1 < Kt) issue(it + 1, cur ^ 1);

#pragma unroll
        for (int ks = 0; ks < 2; ks++) {
            unsigned ah[2][4], al[2][4], bh[2][4], bl[2][4];
#pragma unroll
            for (int mi = 0; mi < 2; mi++) {
                int row = wm + mi * 16 + (lane & 15);
                int c = ks * 2 + (lane >> 4);
                ldsm_x4(ah[mi], &sAh[cur][swzA(row, c)]);
                ldsm_x4(al[mi], &sAl[cur][swzA(row, c)]);
            }
#pragma unroll
            for (int njp = 0; njp < 2; njp++) {
                int krow = ks * 16 + ((lane >> 3) & 1) * 8 + (lane & 7);
                int c = (wn >> 3) + 2 * njp + (lane >> 4);
                ldsm_x4_t(bh[njp], &sBh[cur][swzB(krow, c)]);
                ldsm_x4_t(bl[njp], &sBl[cur][swzB(krow, c)]);
            }
#pragma unroll
            for (int mi = 0; mi < 2; mi++)
#pragma unroll
                for (int njp = 0; njp < 2; njp++)
#pragma unroll
                    for (int sub = 0; sub < 2; sub++) {
                        int nj = njp * 2 + sub;
                        mma_bf16(acc[mi][nj], ah[mi], bh[njp][2*sub], bh[njp][2*sub+1]);
                        mma_bf16(acc[mi][nj], ah[mi], bl[njp][2*sub], bl[njp][2*sub+1]);
                        mma_bf16(acc[mi][nj], al[mi], bh[njp][2*sub], bh[njp][2*sub+1]);
                    }
        }
        __syncthreads();
        cur ^= 1;
    }

#pragma unroll
    for (int mi = 0; mi < 2; mi++) {
        int row0 = m0 + wm + mi * 16 + g;
        int row1 = row0 + 8;
#pragma unroll
        for (int nj = 0; nj < 4; nj++) {
            int col = n0 + wn + nj * 8 + tg * 2;
            if (row0 < M)
                *reinterpret_cast<float2*>(&C[(long)row0 * HDIM + col]) =
                    make_float2(acc[mi][nj][0], acc[mi][nj][1]);
            if (row1 < M)
                *reinterpret_cast<float2*>(&C[(long)row1 * HDIM + col]) =
                    make_float2(acc[mi][nj][2], acc[mi][nj][3]);
        }
    }
}

// ---------------- CSR aggregation (H=256): gather, no atomics ----------------
// out = relu(bias + dinv^2*h[self] + sum_{e in csr[node]} norm_e * h[src_e])
// written as bf16 hi/lo split for the next GEMM/layer. 64 threads per node.
__global__ __launch_bounds__(128)
void k_agg(const float* __restrict__ h, const float* __restrict__ bias,
           __nv_bfloat16* __restrict__ oh, __nv_bfloat16* __restrict__ ol) {
    int node = blockIdx.x * 2 + (threadIdx.x >> 6);
    int f4 = threadIdx.x & 63;
    if (node >= N_NODES) return;
    float d = g_dinv[node];
    float s = d * d;
    float4 acc = __ldg(reinterpret_cast<const float4*>(bias) + f4);
    float4 hv = __ldg(reinterpret_cast<const float4*>(h + (long)node * HDIM) + f4);
    acc.x += s * hv.x; acc.y += s * hv.y; acc.z += s * hv.z; acc.w += s * hv.w;
    int st = g_off[node], en = g_off[node + 1];
    for (int i = st; i < en; i++) {
        int2 ent = __ldg(&g_csr[i]);
        float nrm = __int_as_float(ent.y);
        float4 v = __ldg(reinterpret_cast<const float4*>(h + (long)ent.x * HDIM) + f4);
        acc.x += nrm * v.x; acc.y += nrm * v.y; acc.z += nrm * v.z; acc.w += nrm * v.w;
    }
    // relu + split
    float v[4] = { fmaxf(acc.x, 0.f), fmaxf(acc.y, 0.f), fmaxf(acc.z, 0.f), fmaxf(acc.w, 0.f) };
    unsigned h2[2], l2[2];
    split4(v, h2, l2);
    *reinterpret_cast<uint2*>(&oh[(long)node * HDIM + f4 * 4]) = make_uint2(h2[0], h2[1]);
    *reinterpret_cast<uint2*>(&ol[(long)node * HDIM + f4 * 4]) = make_uint2(l2[0], l2[1]);
}

// ---------------- layer 3: warp-per-row GEMM [N,256]x[256,7] ----------------
__global__ __launch_bounds__(256)
void k_gemm3(const __nv_bfloat16* __restrict__ Ahd, const __nv_bfloat16* __restrict__ Ald,
             const float* __restrict__ W) {
    __shared__ float Ws[HDIM * NCLS];
    int tid = threadIdx.x;
    for (int i = tid; i < HDIM * NCLS; i += 256) Ws[i] = W[i];
    __syncthreads();

    int warp = tid >> 5, lane = tid & 31;
    int row = blockIdx.x * 8 + warp;
    if (row >= N_NODES) return;

    uint4 uh = __ldg(reinterpret_cast<const uint4*>(Ahd + (long)row * HDIM) + lane);
    uint4 ul = __ldg(reinterpret_cast<const uint4*>(Ald + (long)row * HDIM) + lane);
    float v[8];
    {
        const unsigned* hu = reinterpret_cast<const unsigned*>(&uh);
        const unsigned* lu = reinterpret_cast<const unsigned*>(&ul);
#pragma unroll
        for (int p = 0; p < 4; p++) {
            float2 hf = __bfloat1622float2(*reinterpret_cast<const __nv_bfloat162*>(&hu[p]));
            float2 lf = __bfloat1622float2(*reinterpret_cast<const __nv_bfloat162*>(&lu[p]));
            v[2*p] = hf.x + lf.x; v[2*p+1] = hf.y + lf.y;
        }
    }
    int k0 = lane * 8;
    float acc[NCLS];
#pragma unroll
    for (int c = 0; c < NCLS; c++) acc[c] = 0.0f;
#pragma unroll
    for (int j = 0; j < 8; j++)
#pragma unroll
        for (int c = 0; c < NCLS; c++)
            acc[c] = fmaf(v[j], Ws[(k0 + j) * NCLS + c], acc[c]);
#pragma unroll
    for (int c = 0; c < NCLS; c++)
#pragma unroll
        for (int off = 16; off; off >>= 1)
            acc[c] += __shfl_down_sync(0xffffffffu, acc[c], off);
    if (lane == 0) {
#pragma unroll
        for (int c = 0; c < NCLS; c++) g_h3[row * 8 + c] = acc[c];
        g_h3[row * 8 + 7] = 0.0f;
    }
}

__global__ __launch_bounds__(256)
void k_agg3(const float* __restrict__ b3) {
    int node = blockIdx.x * 32 + (threadIdx.x >> 3);
    int c = threadIdx.x & 7;
    if (node >= N_NODES || c >= NCLS) return;
    float d = g_dinv[node];
    float acc = b3[c] + d * d * g_h3[node * 8 + c];
    int st = g_off[node], en = g_off[node + 1];
    for (int i = st; i < en; i++) {
        int2 ent = __ldg(&g_csr[i]);
        acc += __int_as_float(ent.y) * g_h3[ent.x * 8 + c];
    }
    g_a3[node * 8 + c] = acc;
}

__global__ void k_log_softmax(float* __restrict__ out) {
    int i = blockIdx.x * blockDim.x + threadIdx.x;
    if (i >= N_NODES) return;
    float v[NCLS];
    float m = -INFINITY;
#pragma unroll
    for (int c = 0; c < NCLS; c++) { v[c] = g_a3[i * 8 + c]; m = fmaxf(m, v[c]); }
    float s = 0.0f;
#pragma unroll
    for (int c = 0; c < NCLS; c++) s += __expf(v[c] - m);
    float lse = m + __logf(s);
#pragma unroll
    for (int c = 0; c < NCLS; c++) out[i * NCLS + c] = v[c] - lse;
}

// ---------------- launch ----------------
extern "C" void kernel_launch(void* const* d_in, const int* in_sizes, int n_in,
                              void* d_out, int out_size) {
    const float* x  = (const float*)d_in[0];
    const int*   ei = (const int*)d_in[1];
    const float* W1 = (const float*)d_in[2];
    const float* b1 = (const float*)d_in[3];
    const float* W2 = (const float*)d_in[4];
    const float* b2 = (const float*)d_in[5];
    const float* W3 = (const float*)d_in[6];
    const float* b3 = (const float*)d_in[7];
    float* out = (float*)d_out;

    const int E = in_sizes[1] / 2;
    const int* src = ei;
    const int* dst = ei + E;

    __nv_bfloat16 *xh, *xl, *w1h, *w1l, *w2h, *w2l, *a1h, *a1l, *a2h, *a2l;
    float *gh;
    cudaGetSymbolAddress((void**)&xh, g_xh);   cudaGetSymbolAddress((void**)&xl, g_xl);
    cudaGetSymbolAddress((void**)&w1h, g_w1h); cudaGetSymbolAddress((void**)&w1l, g_w1l);
    cudaGetSymbolAddress((void**)&w2h, g_w2h); cudaGetSymbolAddress((void**)&w2l, g_w2l);
    cudaGetSymbolAddress((void**)&a1h, g_a1h); cudaGetSymbolAddress((void**)&a1l, g_a1l);
    cudaGetSymbolAddress((void**)&a2h, g_a2h); cudaGetSymbolAddress((void**)&a2l, g_a2l);
    cudaGetSymbolAddress((void**)&gh, g_h);

    // CSR + norm
    k_zero_cnt<<<(N_NODES + 255) / 256, 256>>>();
    k_cnt_edges<<<(E + 255) / 256, 256>>>(dst, E);
    k_dinv<<<(N_NODES + 255) / 256, 256>>>();
    k_scan<<<1, 1024>>>();
    k_csr_fill<<<(E + 255) / 256, 256>>>(src, dst, E);

    // operand prep
    {
        long tx = (long)N_NODES * (KP1 / 4);
        k_split_x<<<(unsigned)((tx + 255) / 256), 256>>>(x);
        k_split_w<<<(KP1 * 64 + 255) / 256, 256>>>(W1, w1h, w1l, F_IN, KP1);
        k_split_w<<<(HDIM * 64 + 255) / 256, 256>>>(W2, w2h, w2l, HDIM, HDIM);
    }

    dim3 gemm_grid((N_NODES + BM - 1) / BM, HDIM / BN);

    // layer 1
    k_gemm_bf3<<<gemm_grid, 256>>>(xh, xl, w1h, w1l, gh, N_NODES, KP1);
    k_agg<<<(N_NODES + 1) / 2, 128>>>(gh, b1, a1h, a1l);

    // layer 2
    k_gemm_bf3<<<gemm_grid, 256>>>(a1h, a1l, w2h, w2l, gh, N_NODES, HDIM);
    k_agg<<<(N_NODES + 1) / 2, 128>>>(gh, b2, a2h, a2l);

    // layer 3
    k_gemm3<<<(N_NODES + 7) / 8, 256>>>(a2h, a2l, W3);
    k_agg3<<<(N_NODES + 31) / 32, 256>>>(b3);
    k_log_softmax<<<(N_NODES + 255) / 256, 256>>>(out);
}